// round 2
// baseline (speedup 1.0000x reference)
#include <cuda_runtime.h>
#include <cstdint>
#include <cstddef>

// Problem sizes (fixed)
#define BB 4
#define TT 4096
#define CC 1024
#define MM (BB * TT)          // 16384
#define BTC (BB * TT * CC)    // 16,777,216

// ---------------------------------------------------------------------------
// Scratch in device globals (no cudaMalloc allowed). Kernels reference these
// directly by symbol — no cudaGetSymbolAddress in the capture path.
// ---------------------------------------------------------------------------
__device__ __align__(16) float g_k[BTC];
__device__ __align__(16) float g_v[BTC];
__device__ __align__(16) float g_r[BTC];
__device__ __align__(16) float g_wkv[BTC];

// ---------------------------------------------------------------------------
// Helpers
// ---------------------------------------------------------------------------
__device__ __forceinline__ uint32_t f2tf32(float x) {
    uint32_t r;
    asm("cvt.rna.tf32.f32 %0, %1;" : "=r"(r) : "f"(x));
    return r;
}

__device__ __forceinline__ void cp_async4(void* smem_dst, const void* gmem_src) {
    uint32_t s = (uint32_t)__cvta_generic_to_shared(smem_dst);
    asm volatile("cp.async.ca.shared.global [%0], [%1], 4;\n" :: "r"(s), "l"(gmem_src));
}

// Which scratch buffer a GEMM reads/writes (enum instead of pointer args so
// kernels bind to the __device__ globals directly).
enum GemmMode { PROJ_K = 0, PROJ_V = 1, PROJ_R = 2, OUT = 3 };

// ---------------------------------------------------------------------------
// TF32 mma.sync GEMM:  Y[m,n] = act( sum_k A[m,k] * W[n,k] )
//   A: [M,1024] row-major; W: [1024,1024] row-major (torch Linear: x @ W^T)
// Block tile 128(M) x 64(N) x 32(K), 8 warps, warp tile 32x32 (2x4 m16n8k8).
// MODE: PROJ_K/V -> Y = scratch, A = x
//       PROJ_R   -> Y = g_r with sigmoid, A = x
//       OUT      -> A = g_wkv * g_r, Y = d_out
// ---------------------------------------------------------------------------
template<int MODE>
__global__ void __launch_bounds__(256) gemm_tn(const float* __restrict__ Ain,
                                               const float* __restrict__ W,
                                               float* __restrict__ Yout)
{
    constexpr int BM = 128, BN = 64, BK = 32;
    __shared__ uint32_t sA[BM][BK + 1];
    __shared__ uint32_t sB[BN][BK + 1];

    const float* A = (MODE == OUT) ? g_wkv : Ain;
    float* Y;
    if (MODE == PROJ_K)      Y = g_k;
    else if (MODE == PROJ_V) Y = g_v;
    else if (MODE == PROJ_R) Y = g_r;
    else                     Y = Yout;

    const int tid  = threadIdx.x;
    const int m0   = blockIdx.y * BM;
    const int n0   = blockIdx.x * BN;
    const int warp = tid >> 5, lane = tid & 31;
    const int wm   = (warp >> 1) << 5;   // 0,32,64,96
    const int wn   = (warp & 1) << 5;    // 0,32
    const int grp  = lane >> 2, qid = lane & 3;

    float acc[2][4][4];
#pragma unroll
    for (int a = 0; a < 2; a++)
#pragma unroll
        for (int b = 0; b < 4; b++)
#pragma unroll
            for (int c = 0; c < 4; c++) acc[a][b][c] = 0.f;

    for (int k0 = 0; k0 < CC; k0 += BK) {
        // --- stage A tile: 128 x 32 floats = 1024 float4, 4 per thread ---
#pragma unroll
        for (int i = 0; i < 4; i++) {
            int g = tid + (i << 8);
            int r = g >> 3, cc = (g & 7) << 2;
            const size_t off = (size_t)(m0 + r) * CC + k0 + cc;
            float4 v = *(const float4*)(A + off);
            if (MODE == OUT) {
                const float4 v2 = *(const float4*)(g_r + off);
                v.x *= v2.x; v.y *= v2.y; v.z *= v2.z; v.w *= v2.w;
            }
            sA[r][cc + 0] = f2tf32(v.x);
            sA[r][cc + 1] = f2tf32(v.y);
            sA[r][cc + 2] = f2tf32(v.z);
            sA[r][cc + 3] = f2tf32(v.w);
        }
        // --- stage B tile: 64 x 32 floats = 512 float4, 2 per thread ---
#pragma unroll
        for (int i = 0; i < 2; i++) {
            int g = tid + (i << 8);
            int r = g >> 3, cc = (g & 7) << 2;
            const float4 v = *(const float4*)(W + (size_t)(n0 + r) * CC + k0 + cc);
            sB[r][cc + 0] = f2tf32(v.x);
            sB[r][cc + 1] = f2tf32(v.y);
            sB[r][cc + 2] = f2tf32(v.z);
            sB[r][cc + 3] = f2tf32(v.w);
        }
        __syncthreads();

#pragma unroll
        for (int kk = 0; kk < BK; kk += 8) {
            uint32_t af[2][4], bf[4][2];
#pragma unroll
            for (int mt = 0; mt < 2; mt++) {
                int r = wm + (mt << 4) + grp;
                af[mt][0] = sA[r][kk + qid];
                af[mt][1] = sA[r + 8][kk + qid];
                af[mt][2] = sA[r][kk + qid + 4];
                af[mt][3] = sA[r + 8][kk + qid + 4];
            }
#pragma unroll
            for (int nt = 0; nt < 4; nt++) {
                int r = wn + (nt << 3) + grp;
                bf[nt][0] = sB[r][kk + qid];
                bf[nt][1] = sB[r][kk + qid + 4];
            }
#pragma unroll
            for (int mt = 0; mt < 2; mt++)
#pragma unroll
                for (int nt = 0; nt < 4; nt++) {
                    asm volatile(
                        "mma.sync.aligned.m16n8k8.row.col.f32.tf32.tf32.f32 "
                        "{%0,%1,%2,%3}, {%4,%5,%6,%7}, {%8,%9}, {%0,%1,%2,%3};"
                        : "+f"(acc[mt][nt][0]), "+f"(acc[mt][nt][1]),
                          "+f"(acc[mt][nt][2]), "+f"(acc[mt][nt][3])
                        : "r"(af[mt][0]), "r"(af[mt][1]), "r"(af[mt][2]), "r"(af[mt][3]),
                          "r"(bf[nt][0]), "r"(bf[nt][1]));
                }
        }
        __syncthreads();
    }

    // --- epilogue ---
#pragma unroll
    for (int mt = 0; mt < 2; mt++)
#pragma unroll
        for (int nt = 0; nt < 4; nt++) {
            int row = m0 + wm + (mt << 4) + grp;
            int col = n0 + wn + (nt << 3) + (qid << 1);
            float o0 = acc[mt][nt][0], o1 = acc[mt][nt][1];
            float o2 = acc[mt][nt][2], o3 = acc[mt][nt][3];
            if (MODE == PROJ_R) {
                o0 = 1.f / (1.f + expf(-o0));
                o1 = 1.f / (1.f + expf(-o1));
                o2 = 1.f / (1.f + expf(-o2));
                o3 = 1.f / (1.f + expf(-o3));
            }
            *(float2*)(Y + (size_t)row * CC + col)       = make_float2(o0, o1);
            *(float2*)(Y + (size_t)(row + 8) * CC + col) = make_float2(o2, o3);
        }
}

// ---------------------------------------------------------------------------
// WKV scan: exact reference recurrence, one thread per (b,c) channel.
// 64 channels per block, cp.async double-buffered staging of k/v tiles
// (each thread loads & consumes only its own channel -> no __syncthreads).
// ---------------------------------------------------------------------------
constexpr int SCH = 64;   // channels per block
constexpr int STG = 32;   // timesteps per stage
constexpr int NSTAGES = TT / STG;  // 128

__global__ void __launch_bounds__(SCH) wkv_scan(const float* __restrict__ time_decay,
                                                const float* __restrict__ time_first,
                                                const float* __restrict__ aa0,
                                                const float* __restrict__ bb0,
                                                const float* __restrict__ pp0,
                                                float* __restrict__ out_tail)
{
    __shared__ float sK[2][STG][SCH];
    __shared__ float sV[2][STG][SCH];

    const int blk = blockIdx.x;            // 64 blocks = 4 (B) * 16
    const int b   = blk >> 4;
    const int c0  = (blk & 15) * SCH;
    const int tid = threadIdx.x;
    const int c   = c0 + tid;
    const int sidx = b * CC + c;

    const float w = expf(time_decay[c]);
    const float u = time_first[c];
    float aa = aa0[sidx], bb = bb0[sidx], pp = pp0[sidx];

    const float* kbase = g_k   + (size_t)b * TT * CC + c;
    const float* vbase = g_v   + (size_t)b * TT * CC + c;
    float*       wbase = g_wkv + (size_t)b * TT * CC + c;

    // prefetch stage 0
    {
#pragma unroll
        for (int r = 0; r < STG; r++) {
            cp_async4(&sK[0][r][tid], kbase + (size_t)r * CC);
            cp_async4(&sV[0][r][tid], vbase + (size_t)r * CC);
        }
        asm volatile("cp.async.commit_group;\n");
    }

    for (int s = 0; s < NSTAGES; s++) {
        if (s + 1 < NSTAGES) {
            const int nb = (s + 1) & 1;
            const float* kp = kbase + (size_t)(s + 1) * STG * CC;
            const float* vp = vbase + (size_t)(s + 1) * STG * CC;
#pragma unroll
            for (int r = 0; r < STG; r++) {
                cp_async4(&sK[nb][r][tid], kp + (size_t)r * CC);
                cp_async4(&sV[nb][r][tid], vp + (size_t)r * CC);
            }
            asm volatile("cp.async.commit_group;\n");
            asm volatile("cp.async.wait_group 1;\n");
        } else {
            asm volatile("cp.async.wait_group 0;\n");
        }

        const int buf = s & 1;
        float* wp = wbase + (size_t)s * STG * CC;
#pragma unroll 8
        for (int i = 0; i < STG; i++) {
            const float kt = sK[buf][i][tid];
            const float vt = sV[buf][i][tid];
            // output (uses state BEFORE update) — exact reference ops
            const float ww = u + kt;
            const float p  = fmaxf(pp, ww);
            const float e1 = expf(pp - p);
            const float e2 = expf(ww - p);
            wp[(size_t)i * CC] = (e1 * aa + e2 * vt) / (e1 * bb + e2);
            // state update
            const float ww2 = pp - w;
            const float p2  = fmaxf(ww2, kt);
            const float e1b = expf(ww2 - p2);
            const float e2b = expf(kt - p2);
            aa = e1b * aa + e2b * vt;
            bb = e1b * bb + e2b;
            pp = p2;
        }
    }

    // final states (order: aa, bb, pp after the [B,T,C] out block)
    out_tail[sidx]               = aa;
    out_tail[BB * CC + sidx]     = bb;
    out_tail[2 * BB * CC + sidx] = pp;
}

// ---------------------------------------------------------------------------
// Launch
// ---------------------------------------------------------------------------
extern "C" void kernel_launch(void* const* d_in, const int* in_sizes, int n_in,
                              void* d_out, int out_size)
{
    const float* x    = (const float*)d_in[0];
    const float* kw   = (const float*)d_in[1];
    const float* vw   = (const float*)d_in[2];
    const float* rw   = (const float*)d_in[3];
    const float* ow   = (const float*)d_in[4];
    const float* td   = (const float*)d_in[5];
    const float* tf   = (const float*)d_in[6];
    const float* aa0  = (const float*)d_in[7];
    const float* bb0  = (const float*)d_in[8];
    const float* pp0  = (const float*)d_in[9];

    float* out  = (float*)d_out;
    float* tail = out + (size_t)BTC;

    dim3 gg(CC / 64, MM / 128);   // (16, 128)

    gemm_tn<PROJ_K><<<gg, 256>>>(x, kw, nullptr);
    gemm_tn<PROJ_V><<<gg, 256>>>(x, vw, nullptr);
    gemm_tn<PROJ_R><<<gg, 256>>>(x, rw, nullptr);

    wkv_scan<<<BB * (CC / SCH), SCH>>>(td, tf, aa0, bb0, pp0, tail);

    // out = (r * wkv) @ ow^T   (r-multiply fused into A staging)
    gemm_tn<OUT><<<gg, 256>>>(nullptr, ow, out);
}

// round 4
// speedup vs baseline: 1.3333x; 1.3333x over previous
#include <cuda_runtime.h>
#include <cstdint>
#include <cstddef>

// Problem sizes (fixed)
#define BB 4
#define TT 4096
#define CC 1024
#define MM (BB * TT)          // 16384
#define BTC (BB * TT * CC)    // 16,777,216
#define NCH 32                // scan chunks along T
#define CLEN (TT / NCH)       // 128
#define NBC (BB * CC)         // 4096

// ---------------------------------------------------------------------------
// Scratch in device globals (no cudaMalloc allowed)
// ---------------------------------------------------------------------------
__device__ __align__(16) float g_k[BTC];
__device__ __align__(16) float g_v[BTC];
__device__ __align__(16) float g_r[BTC];
__device__ __align__(16) float g_wkv[BTC];
// chunk-local end states (from identity init) and combined incoming states
__device__ float g_saa[NCH][NBC], g_sbb[NCH][NBC], g_spp[NCH][NBC];
__device__ float g_iaa[NCH][NBC], g_ibb[NCH][NBC], g_ipp[NCH][NBC];

// ---------------------------------------------------------------------------
// Helpers
// ---------------------------------------------------------------------------
__device__ __forceinline__ uint32_t f2tf32(float x) {
    uint32_t r;
    asm("cvt.rna.tf32.f32 %0, %1;" : "=r"(r) : "f"(x));
    return r;
}

// ---------------------------------------------------------------------------
// TF32 mma.sync GEMM:  Y[m,n] = act( sum_k A[m,k] * W[n,k] )
// Block tile 128x64x32, 256 threads (8 warps, warp tile 32x32 = 2x4 m16n8k8).
// Double-buffered smem with LDG->reg prefetch. Smem stored in an
// mma-fragment-permuted layout so fragment fetch is vectorized:
//   A frag (per mt,kk): one LDS.128  -> {(g,q),(g+8,q),(g,q+4),(g+8,q+4)}
//   B frag (per nt,kk): one LDS.64   -> {(n,q),(n,q+4)}
// ISOUT=false: fused 3-projection GEMM, blockIdx.z in {0,1,2} selects
//   weight {kw,vw,rw} and destination {g_k,g_v,g_r}; z==2 applies sigmoid.
// ISOUT=true:  A = g_wkv * g_r (fused), W = output_w, Y = d_out.
// ---------------------------------------------------------------------------
template<bool ISOUT>
__global__ void __launch_bounds__(256) gemm_tn(const float* __restrict__ A0,
                                               const float* __restrict__ W0,
                                               const float* __restrict__ W1,
                                               const float* __restrict__ W2,
                                               float* __restrict__ Yout)
{
    // [buf][m-block16][kk-block][grp][qid][slot]
    __shared__ __align__(16) uint32_t sA[2][8][4][8][4][4];   // 32 KB
    // [buf][n-block8][kk-block][grp][qid][hi]
    __shared__ __align__(16) uint32_t sB[2][8][4][8][4][2];   // 16 KB

    const int z = blockIdx.z;
    const float* A = ISOUT ? g_wkv : A0;
    const float* W = ISOUT ? W0 : (z == 0 ? W0 : (z == 1 ? W1 : W2));
    float* Y       = ISOUT ? Yout : (z == 0 ? g_k : (z == 1 ? g_v : g_r));

    const int tid  = threadIdx.x;
    const int m0   = blockIdx.y * 128;
    const int n0   = blockIdx.x * 64;
    const int warp = tid >> 5, lane = tid & 31;
    const int wmb  = (warp >> 1) << 1;   // m block16 index base (0,2,4,6)
    const int wnb  = (warp & 1) << 2;    // n block8  index base (0,4)
    const int grp  = lane >> 2, qid = lane & 3;

    // staging coordinates (A: 4 float4/thread, B: 2 float4/thread)
    int aR_[4], aC_[4], bR_[2], bC_[2];
#pragma unroll
    for (int i = 0; i < 4; i++) { int g = tid + (i << 8); aR_[i] = g >> 3; aC_[i] = (g & 7) << 2; }
#pragma unroll
    for (int i = 0; i < 2; i++) { int g = tid + (i << 8); bR_[i] = g >> 3; bC_[i] = (g & 7) << 2; }

    float4 aReg[4], bReg[2];

    auto load_tile = [&](int k0) {
#pragma unroll
        for (int i = 0; i < 4; i++) {
            const size_t off = (size_t)(m0 + aR_[i]) * CC + k0 + aC_[i];
            float4 v = *(const float4*)(A + off);
            if (ISOUT) {
                const float4 v2 = *(const float4*)(g_r + off);
                v.x *= v2.x; v.y *= v2.y; v.z *= v2.z; v.w *= v2.w;
            }
            aReg[i] = v;
        }
#pragma unroll
        for (int i = 0; i < 2; i++)
            bReg[i] = *(const float4*)(W + (size_t)(n0 + bR_[i]) * CC + k0 + bC_[i]);
    };

    auto store_tile = [&](int buf) {
#pragma unroll
        for (int i = 0; i < 4; i++) {
            const int r = aR_[i], cc = aC_[i];
            const int blk = r >> 4, gs = r & 7, mhi = (r >> 3) & 1;
            const int kkb = cc >> 3, hi = (cc >> 2) & 1, slot = (hi << 1) + mhi;
            const float* v = (const float*)&aReg[i];
#pragma unroll
            for (int j = 0; j < 4; j++)
                sA[buf][blk][kkb][gs][j][slot] = f2tf32(v[j]);
        }
#pragma unroll
        for (int i = 0; i < 2; i++) {
            const int r = bR_[i], cc = bC_[i];
            const int blk = r >> 3, gs = r & 7;
            const int kkb = cc >> 3, hi = (cc >> 2) & 1;
            const float* v = (const float*)&bReg[i];
#pragma unroll
            for (int j = 0; j < 4; j++)
                sB[buf][blk][kkb][gs][j][hi] = f2tf32(v[j]);
        }
    };

    float acc[2][4][4];
#pragma unroll
    for (int a = 0; a < 2; a++)
#pragma unroll
        for (int b = 0; b < 4; b++)
#pragma unroll
            for (int c = 0; c < 4; c++) acc[a][b][c] = 0.f;

    load_tile(0);
    store_tile(0);
    __syncthreads();

    int buf = 0;
    for (int k0 = 0; k0 < CC; k0 += 32) {
        const bool notlast = (k0 + 32 < CC);
        if (notlast) load_tile(k0 + 32);

#pragma unroll
        for (int kkb = 0; kkb < 4; kkb++) {
            uint32_t af[2][4], bf[4][2];
#pragma unroll
            for (int mt = 0; mt < 2; mt++)
                *(uint4*)af[mt] = *(const uint4*)&sA[buf][wmb + mt][kkb][grp][qid][0];
#pragma unroll
            for (int nt = 0; nt < 4; nt++)
                *(uint2*)bf[nt] = *(const uint2*)&sB[buf][wnb + nt][kkb][grp][qid][0];
#pragma unroll
            for (int mt = 0; mt < 2; mt++)
#pragma unroll
                for (int nt = 0; nt < 4; nt++) {
                    asm volatile(
                        "mma.sync.aligned.m16n8k8.row.col.f32.tf32.tf32.f32 "
                        "{%0,%1,%2,%3}, {%4,%5,%6,%7}, {%8,%9}, {%0,%1,%2,%3};"
                        : "+f"(acc[mt][nt][0]), "+f"(acc[mt][nt][1]),
                          "+f"(acc[mt][nt][2]), "+f"(acc[mt][nt][3])
                        : "r"(af[mt][0]), "r"(af[mt][1]), "r"(af[mt][2]), "r"(af[mt][3]),
                          "r"(bf[nt][0]), "r"(bf[nt][1]));
                }
        }

        if (notlast) {
            store_tile(buf ^ 1);
            __syncthreads();
        }
        buf ^= 1;
    }

    // --- epilogue ---
#pragma unroll
    for (int mt = 0; mt < 2; mt++)
#pragma unroll
        for (int nt = 0; nt < 4; nt++) {
            const int row = m0 + ((wmb + mt) << 4) + grp;
            const int col = n0 + ((wnb + nt) << 3) + (qid << 1);
            float o0 = acc[mt][nt][0], o1 = acc[mt][nt][1];
            float o2 = acc[mt][nt][2], o3 = acc[mt][nt][3];
            if (!ISOUT && z == 2) {
                o0 = 1.f / (1.f + __expf(-o0));
                o1 = 1.f / (1.f + __expf(-o1));
                o2 = 1.f / (1.f + __expf(-o2));
                o3 = 1.f / (1.f + __expf(-o3));
            }
            *(float2*)(Y + (size_t)row * CC + col)       = make_float2(o0, o1);
            *(float2*)(Y + (size_t)(row + 8) * CC + col) = make_float2(o2, o3);
        }
}

// ---------------------------------------------------------------------------
// WKV chunked parallel scan.
// The stabilized state (aa,bb,pp) represents (aa*e^pp, bb*e^pp); the per-step
// update is linear in that representation, so chunks compose:
//   state_out = decay^n(state_in) (+) state_local(identity-init)
// Pass 1: per-chunk local end states. Pass 2: sequential merge over 32 chunks
// per channel (cheap). Pass 3: exact reference-op replay per chunk with the
// correct incoming state, writing wkv (and tail states from the last chunk).
// ---------------------------------------------------------------------------
__global__ void __launch_bounds__(256) scan_states(const float* __restrict__ td)
{
    const int bid   = blockIdx.x;            // 512 blocks
    const int b     = bid >> 7;
    const int chunk = (bid >> 2) & 31;
    const int c     = ((bid & 3) << 8) + threadIdx.x;

    const float w = expf(td[c]);
    const size_t base = (size_t)b * TT * CC + (size_t)chunk * CLEN * CC + c;
    const float* kp = g_k + base;
    const float* vp = g_v + base;

    float aa = 0.f, bb = 0.f, pp = -1e38f;
#pragma unroll 4
    for (int t = 0; t < CLEN; t++) {
        const float kt = kp[(size_t)t * CC];
        const float vt = vp[(size_t)t * CC];
        const float ww2 = pp - w;
        const float p2  = fmaxf(ww2, kt);
        const float e1b = __expf(ww2 - p2);
        const float e2b = __expf(kt - p2);
        aa = e1b * aa + e2b * vt;
        bb = e1b * bb + e2b;
        pp = p2;
    }
    const int i = b * CC + c;
    g_saa[chunk][i] = aa; g_sbb[chunk][i] = bb; g_spp[chunk][i] = pp;
}

__global__ void __launch_bounds__(256) scan_combine(const float* __restrict__ td,
                                                    const float* __restrict__ aa0,
                                                    const float* __restrict__ bb0,
                                                    const float* __restrict__ pp0)
{
    const int i = blockIdx.x * 256 + threadIdx.x;   // [0, 4096)
    const int c = i & (CC - 1);
    const float w   = expf(td[c]);
    const float dec = (float)CLEN * w;

    float aa = aa0[i], bb = bb0[i], pp = pp0[i];
#pragma unroll
    for (int ch = 0; ch < NCH; ch++) {
        g_iaa[ch][i] = aa; g_ibb[ch][i] = bb; g_ipp[ch][i] = pp;
        const float ppd = pp - dec;
        const float aL = g_saa[ch][i], bL = g_sbb[ch][i], pL = g_spp[ch][i];
        const float p  = fmaxf(ppd, pL);
        const float e1 = __expf(ppd - p);
        const float e2 = __expf(pL - p);
        aa = e1 * aa + e2 * aL;
        bb = e1 * bb + e2 * bL;
        pp = p;
    }
}

__global__ void __launch_bounds__(256) scan_out(const float* __restrict__ td,
                                                const float* __restrict__ tf,
                                                float* __restrict__ out_tail)
{
    const int bid   = blockIdx.x;            // 512 blocks
    const int b     = bid >> 7;
    const int chunk = (bid >> 2) & 31;
    const int c     = ((bid & 3) << 8) + threadIdx.x;
    const int i     = b * CC + c;

    const float w = expf(td[c]);
    const float u = tf[c];
    float aa = g_iaa[chunk][i], bb = g_ibb[chunk][i], pp = g_ipp[chunk][i];

    const size_t base = (size_t)b * TT * CC + (size_t)chunk * CLEN * CC + c;
    const float* kp = g_k + base;
    const float* vp = g_v + base;
    float*       wp = g_wkv + base;

#pragma unroll 4
    for (int t = 0; t < CLEN; t++) {
        const float kt = kp[(size_t)t * CC];
        const float vt = vp[(size_t)t * CC];
        // output (state BEFORE update) — reference op sequence
        const float ww = u + kt;
        const float p  = fmaxf(pp, ww);
        const float e1 = __expf(pp - p);
        const float e2 = __expf(ww - p);
        wp[(size_t)t * CC] = __fdividef(e1 * aa + e2 * vt, e1 * bb + e2);
        // state update
        const float ww2 = pp - w;
        const float p2  = fmaxf(ww2, kt);
        const float e1b = __expf(ww2 - p2);
        const float e2b = __expf(kt - p2);
        aa = e1b * aa + e2b * vt;
        bb = e1b * bb + e2b;
        pp = p2;
    }

    if (chunk == NCH - 1) {
        out_tail[i]           = aa;
        out_tail[NBC + i]     = bb;
        out_tail[2 * NBC + i] = pp;
    }
}

// ---------------------------------------------------------------------------
// Launch
// ---------------------------------------------------------------------------
extern "C" void kernel_launch(void* const* d_in, const int* in_sizes, int n_in,
                              void* d_out, int out_size)
{
    const float* x    = (const float*)d_in[0];
    const float* kw   = (const float*)d_in[1];
    const float* vw   = (const float*)d_in[2];
    const float* rw   = (const float*)d_in[3];
    const float* ow   = (const float*)d_in[4];
    const float* td   = (const float*)d_in[5];
    const float* tf   = (const float*)d_in[6];
    const float* aa0  = (const float*)d_in[7];
    const float* bb0  = (const float*)d_in[8];
    const float* pp0  = (const float*)d_in[9];

    float* out  = (float*)d_out;
    float* tail = out + (size_t)BTC;

    // fused k/v/r projections (z selects weight/output/activation)
    gemm_tn<false><<<dim3(16, 128, 3), 256>>>(x, kw, vw, rw, nullptr);

    // chunked parallel WKV scan
    scan_states<<<512, 256>>>(td);
    scan_combine<<<16, 256>>>(td, aa0, bb0, pp0);
    scan_out<<<512, 256>>>(td, tf, tail);

    // out = (r * wkv) @ ow^T  (r-multiply fused into A staging)
    gemm_tn<true><<<dim3(16, 128, 1), 256>>>(nullptr, ow, nullptr, nullptr, out);
}

// round 6
// speedup vs baseline: 3.1425x; 2.3569x over previous
#include <cuda_runtime.h>
#include <cstdint>
#include <cstddef>

// Problem sizes (fixed)
#define BB 4
#define TT 4096
#define CC 1024
#define MM (BB * TT)          // 16384
#define BTC (BB * TT * CC)    // 16,777,216
#define NCH 32                // scan chunks along T
#define CLEN (TT / NCH)       // 128
#define NBC (BB * CC)         // 4096
#define WSZ (CC * CC)         // 1,048,576

// ---------------------------------------------------------------------------
// Scratch in device globals (no cudaMalloc allowed)
// g_x / g_wkv / weights are stored TF32-rounded AND fragment-permuted so the
// GEMM mainloop is pure cp.async -> vectorized LDS -> mma.sync.
// ---------------------------------------------------------------------------
__device__ __align__(16) float g_k[BTC];
__device__ __align__(16) float g_v[BTC];
__device__ __align__(16) float g_r[BTC];
__device__ __align__(16) float g_wkv[BTC];   // permuted tf32 (r*wkv)
__device__ __align__(16) float g_x[BTC];     // permuted tf32 x
__device__ __align__(16) float g_wk[WSZ], g_wv[WSZ], g_wr2[WSZ], g_wo[WSZ];
// chunk-local end states (from identity init) and combined incoming states
__device__ float g_saa[NCH][NBC], g_sbb[NCH][NBC], g_spp[NCH][NBC];
__device__ float g_iaa[NCH][NBC], g_ibb[NCH][NBC], g_ipp[NCH][NBC];

// ---------------------------------------------------------------------------
// Helpers
// ---------------------------------------------------------------------------
__device__ __forceinline__ uint32_t f2tf32(float x) {
    uint32_t r;
    asm("cvt.rna.tf32.f32 %0, %1;" : "=r"(r) : "f"(x));
    return r;
}
__device__ __forceinline__ uint32_t smem_u32(const void* p) {
    return (uint32_t)__cvta_generic_to_shared(p);
}
__device__ __forceinline__ void cp16(uint32_t smem_dst, const void* gmem_src) {
    asm volatile("cp.async.cg.shared.global [%0], [%1], 16;\n" :: "r"(smem_dst), "l"(gmem_src));
}
__device__ __forceinline__ void cp_commit() { asm volatile("cp.async.commit_group;\n"); }
template<int N>
__device__ __forceinline__ void cp_wait() { asm volatile("cp.async.wait_group %0;\n" :: "n"(N)); }

// Fragment-permuted tile layouts (word index within the buffer).
// A tile: per (mblk=m>>7, kblk=c>>5): 4096 floats.
//   word = (r>>4)*512 + (k>>3)*128 + (r&7)*16 + (k&3)*4 + ((k>>2)&1)*2 + ((r>>3)&1)
// B tile: per (nblk=n>>6, kblk=c>>5): 2048 floats.
//   word = (r>>3)*256 + (k>>3)*64 + (r&7)*8 + (k&3)*2 + ((k>>2)&1)
__device__ __forceinline__ size_t a_perm_idx(int m, int c) {
    const int mblk = m >> 7, kblk = c >> 5, r = m & 127, k = c & 31;
    return (size_t)(mblk * 32 + kblk) * 4096 +
           ((r >> 4) << 9) + ((k >> 3) << 7) + ((r & 7) << 4) +
           ((k & 3) << 2) + (((k >> 2) & 1) << 1) + ((r >> 3) & 1);
}
__device__ __forceinline__ size_t b_perm_idx(int n, int c) {
    const int nblk = n >> 6, kblk = c >> 5, r = n & 63, k = c & 31;
    return (size_t)(nblk * 32 + kblk) * 2048 +
           ((r >> 3) << 8) + ((k >> 3) << 6) + ((r & 7) << 3) +
           ((k & 3) << 1) + ((k >> 2) & 1);
}

// ---------------------------------------------------------------------------
// Pre-passes: tf32-round + fragment-permute into gmem
// ---------------------------------------------------------------------------
__global__ void __launch_bounds__(256) round_x(const float* __restrict__ x)
{
    const int n4 = BTC / 4;
    for (int f = blockIdx.x * 256 + threadIdx.x; f < n4; f += gridDim.x * 256) {
        const int m = f >> 8, c0 = (f & 255) << 2;
        const float4 v = ((const float4*)x)[f];
        const size_t base = a_perm_idx(m, c0);
        g_x[base + 0]  = __uint_as_float(f2tf32(v.x));
        g_x[base + 4]  = __uint_as_float(f2tf32(v.y));
        g_x[base + 8]  = __uint_as_float(f2tf32(v.z));
        g_x[base + 12] = __uint_as_float(f2tf32(v.w));
    }
}

__global__ void __launch_bounds__(256) round_w(const float* __restrict__ kw,
                                               const float* __restrict__ vw,
                                               const float* __restrict__ rw,
                                               const float* __restrict__ ow)
{
    const int z = blockIdx.y;
    const float* src = z == 0 ? kw : (z == 1 ? vw : (z == 2 ? rw : ow));
    float* dst       = z == 0 ? g_wk : (z == 1 ? g_wv : (z == 2 ? g_wr2 : g_wo));
    const int n4 = WSZ / 4;
    for (int f = blockIdx.x * 256 + threadIdx.x; f < n4; f += gridDim.x * 256) {
        const int n = f >> 8, c0 = (f & 255) << 2;
        const float4 v = ((const float4*)src)[f];
        const size_t base = b_perm_idx(n, c0);
        dst[base + 0] = __uint_as_float(f2tf32(v.x));
        dst[base + 2] = __uint_as_float(f2tf32(v.y));
        dst[base + 4] = __uint_as_float(f2tf32(v.z));
        dst[base + 6] = __uint_as_float(f2tf32(v.w));
    }
}

// ---------------------------------------------------------------------------
// TF32 mma.sync GEMM, cp.async 4-stage pipeline over permuted gmem tiles.
// Block tile 128(M) x 64(N) x 32(K), 256 threads, warp tile 32x32 (2x4 m16n8k8).
// Fragment fetch: A = LDS.128, B = LDS.64 (proven layout from R4).
// ---------------------------------------------------------------------------
#define STAGES 4
#define STGW 6144            // words per stage: 4096 A + 2048 B
#define STGB 24576           // bytes per stage

template<bool ISOUT>
__global__ void __launch_bounds__(256) gemm_mm(float* __restrict__ Yout)
{
    extern __shared__ __align__(16) uint32_t dsm[];   // STAGES*STGW words = 96 KB

    const int z = blockIdx.z;
    const float* A = ISOUT ? g_wkv : g_x;
    const float* W = ISOUT ? g_wo : (z == 0 ? g_wk : (z == 1 ? g_wv : g_wr2));
    float* Y       = ISOUT ? Yout : (z == 0 ? g_k : (z == 1 ? g_v : g_r));

    const int tid  = threadIdx.x;
    const int warp = tid >> 5, lane = tid & 31;
    const int mblk = blockIdx.y, nblk = blockIdx.x;
    const int wmb  = (warp >> 1) << 1;   // m block16 base (0,2,4,6)
    const int wnb  = (warp & 1) << 2;    // n block8 base (0,4)
    const int grp  = lane >> 2, qid = lane & 3;

    const uint32_t sbase = smem_u32(dsm);

    auto load_stage = [&](int slot, int kblk) {
        const uint32_t sb = sbase + slot * STGB;
        const float* at = A + (size_t)(mblk * 32 + kblk) * 4096;
        const float* bt = W + (size_t)(nblk * 32 + kblk) * 2048;
#pragma unroll
        for (int i = 0; i < 4; i++) {               // 1024 A chunks
            const int ch = tid + (i << 8);
            cp16(sb + ch * 16, at + ch * 4);
        }
#pragma unroll
        for (int i = 0; i < 2; i++) {               // 512 B chunks
            const int ch = tid + (i << 8);
            cp16(sb + 16384 + ch * 16, bt + ch * 4);
        }
    };

    float acc[2][4][4];
#pragma unroll
    for (int a = 0; a < 2; a++)
#pragma unroll
        for (int b = 0; b < 4; b++)
#pragma unroll
            for (int c = 0; c < 4; c++) acc[a][b][c] = 0.f;

#pragma unroll
    for (int s = 0; s < 3; s++) { load_stage(s, s); cp_commit(); }

    for (int i = 0; i < 32; i++) {
        if (i < 30)       cp_wait<2>();
        else if (i == 30) cp_wait<1>();
        else              cp_wait<0>();
        __syncthreads();

        if (i + 3 < 32) { load_stage((i + 3) & 3, i + 3); cp_commit(); }

        const uint32_t* stA = dsm + (i & 3) * STGW;
        const uint32_t* stB = stA + 4096;
#pragma unroll
        for (int kkb = 0; kkb < 4; kkb++) {
            uint32_t af[2][4], bf[4][2];
#pragma unroll
            for (int mt = 0; mt < 2; mt++)
                *(uint4*)af[mt] =
                    *(const uint4*)&stA[((wmb + mt) << 9) + (kkb << 7) + (grp << 4) + (qid << 2)];
#pragma unroll
            for (int nt = 0; nt < 4; nt++)
                *(uint2*)bf[nt] =
                    *(const uint2*)&stB[((wnb + nt) << 8) + (kkb << 6) + (grp << 3) + (qid << 1)];
#pragma unroll
            for (int mt = 0; mt < 2; mt++)
#pragma unroll
                for (int nt = 0; nt < 4; nt++) {
                    asm volatile(
                        "mma.sync.aligned.m16n8k8.row.col.f32.tf32.tf32.f32 "
                        "{%0,%1,%2,%3}, {%4,%5,%6,%7}, {%8,%9}, {%0,%1,%2,%3};"
                        : "+f"(acc[mt][nt][0]), "+f"(acc[mt][nt][1]),
                          "+f"(acc[mt][nt][2]), "+f"(acc[mt][nt][3])
                        : "r"(af[mt][0]), "r"(af[mt][1]), "r"(af[mt][2]), "r"(af[mt][3]),
                          "r"(bf[nt][0]), "r"(bf[nt][1]));
                }
        }
    }

    // --- epilogue (linear output) ---
    const int m0 = mblk * 128, n0 = nblk * 64;
#pragma unroll
    for (int mt = 0; mt < 2; mt++)
#pragma unroll
        for (int nt = 0; nt < 4; nt++) {
            const int row = m0 + ((wmb + mt) << 4) + grp;
            const int col = n0 + ((wnb + nt) << 3) + (qid << 1);
            float o0 = acc[mt][nt][0], o1 = acc[mt][nt][1];
            float o2 = acc[mt][nt][2], o3 = acc[mt][nt][3];
            if (!ISOUT && z == 2) {
                o0 = 1.f / (1.f + __expf(-o0));
                o1 = 1.f / (1.f + __expf(-o1));
                o2 = 1.f / (1.f + __expf(-o2));
                o3 = 1.f / (1.f + __expf(-o3));
            }
            *(float2*)(Y + (size_t)row * CC + col)       = make_float2(o0, o1);
            *(float2*)(Y + (size_t)(row + 8) * CC + col) = make_float2(o2, o3);
        }
}

// ---------------------------------------------------------------------------
// WKV chunked parallel scan (math unchanged from the passing R4 kernel;
// scan_out fuses r-multiply + tf32 rounding + permuted write for OUT GEMM).
// ---------------------------------------------------------------------------
__global__ void __launch_bounds__(256) scan_states(const float* __restrict__ td)
{
    const int bid   = blockIdx.x;            // 512 blocks
    const int b     = bid >> 7;
    const int chunk = (bid >> 2) & 31;
    const int c     = ((bid & 3) << 8) + threadIdx.x;

    const float w = expf(td[c]);
    const size_t base = (size_t)b * TT * CC + (size_t)chunk * CLEN * CC + c;
    const float* kp = g_k + base;
    const float* vp = g_v + base;

    float aa = 0.f, bb = 0.f, pp = -1e38f;
#pragma unroll 4
    for (int t = 0; t < CLEN; t++) {
        const float kt = kp[(size_t)t * CC];
        const float vt = vp[(size_t)t * CC];
        const float ww2 = pp - w;
        const float p2  = fmaxf(ww2, kt);
        const float e1b = __expf(ww2 - p2);
        const float e2b = __expf(kt - p2);
        aa = e1b * aa + e2b * vt;
        bb = e1b * bb + e2b;
        pp = p2;
    }
    const int i = b * CC + c;
    g_saa[chunk][i] = aa; g_sbb[chunk][i] = bb; g_spp[chunk][i] = pp;
}

__global__ void __launch_bounds__(256) scan_combine(const float* __restrict__ td,
                                                    const float* __restrict__ aa0,
                                                    const float* __restrict__ bb0,
                                                    const float* __restrict__ pp0)
{
    const int i = blockIdx.x * 256 + threadIdx.x;   // [0, 4096)
    const int c = i & (CC - 1);
    const float w   = expf(td[c]);
    const float dec = (float)CLEN * w;

    float aa = aa0[i], bb = bb0[i], pp = pp0[i];
#pragma unroll
    for (int ch = 0; ch < NCH; ch++) {
        g_iaa[ch][i] = aa; g_ibb[ch][i] = bb; g_ipp[ch][i] = pp;
        const float ppd = pp - dec;
        const float aL = g_saa[ch][i], bL = g_sbb[ch][i], pL = g_spp[ch][i];
        const float p  = fmaxf(ppd, pL);
        const float e1 = __expf(ppd - p);
        const float e2 = __expf(pL - p);
        aa = e1 * aa + e2 * aL;
        bb = e1 * bb + e2 * bL;
        pp = p;
    }
}

__global__ void __launch_bounds__(256) scan_out(const float* __restrict__ td,
                                                const float* __restrict__ tf,
                                                float* __restrict__ out_tail)
{
    const int bid   = blockIdx.x;            // 512 blocks
    const int b     = bid >> 7;
    const int chunk = (bid >> 2) & 31;
    const int c     = ((bid & 3) << 8) + threadIdx.x;
    const int i     = b * CC + c;

    const float w = expf(td[c]);
    const float u = tf[c];
    float aa = g_iaa[chunk][i], bb = g_ibb[chunk][i], pp = g_ipp[chunk][i];

    const size_t base = (size_t)b * TT * CC + (size_t)chunk * CLEN * CC + c;
    const float* kp = g_k + base;
    const float* vp = g_v + base;
    const float* rp = g_r + base;
    const int mbase = b * TT + chunk * CLEN;

#pragma unroll 4
    for (int t = 0; t < CLEN; t++) {
        const float kt = kp[(size_t)t * CC];
        const float vt = vp[(size_t)t * CC];
        // output (state BEFORE update) — reference op sequence
        const float ww = u + kt;
        const float p  = fmaxf(pp, ww);
        const float e1 = __expf(pp - p);
        const float e2 = __expf(ww - p);
        const float wkv = __fdividef(e1 * aa + e2 * vt, e1 * bb + e2);
        // fused r-multiply + tf32 rounding + permuted write for OUT GEMM
        g_wkv[a_perm_idx(mbase + t, c)] =
            __uint_as_float(f2tf32(rp[(size_t)t * CC] * wkv));
        // state update
        const float ww2 = pp - w;
        const float p2  = fmaxf(ww2, kt);
        const float e1b = __expf(ww2 - p2);
        const float e2b = __expf(kt - p2);
        aa = e1b * aa + e2b * vt;
        bb = e1b * bb + e2b;
        pp = p2;
    }

    if (chunk == NCH - 1) {
        out_tail[i]           = aa;
        out_tail[NBC + i]     = bb;
        out_tail[2 * NBC + i] = pp;
    }
}

// ---------------------------------------------------------------------------
// Launch
// ---------------------------------------------------------------------------
extern "C" void kernel_launch(void* const* d_in, const int* in_sizes, int n_in,
                              void* d_out, int out_size)
{
    const float* x    = (const float*)d_in[0];
    const float* kw   = (const float*)d_in[1];
    const float* vw   = (const float*)d_in[2];
    const float* rw   = (const float*)d_in[3];
    const float* ow   = (const float*)d_in[4];
    const float* td   = (const float*)d_in[5];
    const float* tf   = (const float*)d_in[6];
    const float* aa0  = (const float*)d_in[7];
    const float* bb0  = (const float*)d_in[8];
    const float* pp0  = (const float*)d_in[9];

    float* out  = (float*)d_out;
    float* tail = out + (size_t)BTC;

    static bool configured = false;
    if (!configured) {
        cudaFuncSetAttribute(gemm_mm<false>, cudaFuncAttributeMaxDynamicSharedMemorySize,
                             STAGES * STGB);
        cudaFuncSetAttribute(gemm_mm<true>,  cudaFuncAttributeMaxDynamicSharedMemorySize,
                             STAGES * STGB);
        configured = true;
    }

    // pre-round to tf32 + fragment-permute into gmem
    round_x<<<2048, 256>>>(x);
    round_w<<<dim3(64, 4), 256>>>(kw, vw, rw, ow);

    // fused k/v/r projections
    gemm_mm<false><<<dim3(16, 128, 3), 256, STAGES * STGB>>>(nullptr);

    // chunked parallel WKV scan
    scan_states<<<512, 256>>>(td);
    scan_combine<<<16, 256>>>(td, aa0, bb0, pp0);
    scan_out<<<512, 256>>>(td, tf, tail);

    // out = (r * wkv) @ ow^T  (A pre-multiplied, rounded, permuted by scan_out)
    gemm_mm<true><<<dim3(16, 128, 1), 256, STAGES * STGB>>>(out);
}

// round 7
// speedup vs baseline: 3.1891x; 1.0148x over previous
#include <cuda_runtime.h>
#include <cstdint>
#include <cstddef>

// Problem sizes (fixed)
#define BB 4
#define TT 4096
#define CC 1024
#define MM (BB * TT)          // 16384
#define BTC (BB * TT * CC)    // 16,777,216
#define NCH 32                // scan chunks along T
#define CLEN (TT / NCH)       // 128
#define NBC (BB * CC)         // 4096
#define WSZ (CC * CC)         // 1,048,576

// ---------------------------------------------------------------------------
// Scratch in device globals (no cudaMalloc allowed)
// g_x / g_wkv / weights are stored TF32-rounded AND fragment-permuted so the
// GEMM mainloop is pure cp.async -> vectorized LDS -> mma.sync.
// ---------------------------------------------------------------------------
__device__ __align__(16) float g_k[BTC];
__device__ __align__(16) float g_v[BTC];
__device__ __align__(16) float g_r[BTC];
__device__ __align__(16) float g_wkv[BTC];   // permuted tf32 (r*wkv)
__device__ __align__(16) float g_x[BTC];     // permuted tf32 x
__device__ __align__(16) float g_wk[WSZ], g_wv[WSZ], g_wr2[WSZ], g_wo[WSZ];
// chunk-local end states (from identity init) and combined incoming states
__device__ float g_saa[NCH][NBC], g_sbb[NCH][NBC], g_spp[NCH][NBC];
__device__ float g_iaa[NCH][NBC], g_ibb[NCH][NBC], g_ipp[NCH][NBC];

// ---------------------------------------------------------------------------
// Helpers
// ---------------------------------------------------------------------------
__device__ __forceinline__ uint32_t f2tf32(float x) {
    uint32_t r;
    asm("cvt.rna.tf32.f32 %0, %1;" : "=r"(r) : "f"(x));
    return r;
}
__device__ __forceinline__ uint32_t smem_u32(const void* p) {
    return (uint32_t)__cvta_generic_to_shared(p);
}
__device__ __forceinline__ void cp16(uint32_t smem_dst, const void* gmem_src) {
    asm volatile("cp.async.cg.shared.global [%0], [%1], 16;\n" :: "r"(smem_dst), "l"(gmem_src));
}
__device__ __forceinline__ void cp_commit() { asm volatile("cp.async.commit_group;\n"); }
template<int N>
__device__ __forceinline__ void cp_wait() { asm volatile("cp.async.wait_group %0;\n" :: "n"(N)); }

// Fragment-permuted tile layouts (word index within the buffer).
// A tile: per (mblk=m>>7, kblk=c>>5): 4096 floats.
//   word = (r>>4)*512 + (k>>3)*128 + (r&7)*16 + (k&3)*4 + ((k>>2)&1)*2 + ((r>>3)&1)
// B tile: per (nblk=n>>6, kblk=c>>5): 2048 floats.
//   word = (r>>3)*256 + (k>>3)*64 + (r&7)*8 + (k&3)*2 + ((k>>2)&1)
__device__ __forceinline__ size_t a_perm_idx(int m, int c) {
    const int mblk = m >> 7, kblk = c >> 5, r = m & 127, k = c & 31;
    return (size_t)(mblk * 32 + kblk) * 4096 +
           ((r >> 4) << 9) + ((k >> 3) << 7) + ((r & 7) << 4) +
           ((k & 3) << 2) + (((k >> 2) & 1) << 1) + ((r >> 3) & 1);
}
__device__ __forceinline__ size_t b_perm_idx(int n, int c) {
    const int nblk = n >> 6, kblk = c >> 5, r = n & 63, k = c & 31;
    return (size_t)(nblk * 32 + kblk) * 2048 +
           ((r >> 3) << 8) + ((k >> 3) << 6) + ((r & 7) << 3) +
           ((k & 3) << 1) + ((k >> 2) & 1);
}

// ---------------------------------------------------------------------------
// Pre-passes: tf32-round + fragment-permute into gmem
// ---------------------------------------------------------------------------
__global__ void __launch_bounds__(256) round_x(const float* __restrict__ x)
{
    const int n4 = BTC / 4;
    for (int f = blockIdx.x * 256 + threadIdx.x; f < n4; f += gridDim.x * 256) {
        const int m = f >> 8, c0 = (f & 255) << 2;
        const float4 v = ((const float4*)x)[f];
        const size_t base = a_perm_idx(m, c0);
        g_x[base + 0]  = __uint_as_float(f2tf32(v.x));
        g_x[base + 4]  = __uint_as_float(f2tf32(v.y));
        g_x[base + 8]  = __uint_as_float(f2tf32(v.z));
        g_x[base + 12] = __uint_as_float(f2tf32(v.w));
    }
}

__global__ void __launch_bounds__(256) round_w(const float* __restrict__ kw,
                                               const float* __restrict__ vw,
                                               const float* __restrict__ rw,
                                               const float* __restrict__ ow)
{
    const int z = blockIdx.y;
    const float* src = z == 0 ? kw : (z == 1 ? vw : (z == 2 ? rw : ow));
    float* dst       = z == 0 ? g_wk : (z == 1 ? g_wv : (z == 2 ? g_wr2 : g_wo));
    const int n4 = WSZ / 4;
    for (int f = blockIdx.x * 256 + threadIdx.x; f < n4; f += gridDim.x * 256) {
        const int n = f >> 8, c0 = (f & 255) << 2;
        const float4 v = ((const float4*)src)[f];
        const size_t base = b_perm_idx(n, c0);
        dst[base + 0] = __uint_as_float(f2tf32(v.x));
        dst[base + 2] = __uint_as_float(f2tf32(v.y));
        dst[base + 4] = __uint_as_float(f2tf32(v.z));
        dst[base + 6] = __uint_as_float(f2tf32(v.w));
    }
}

// ---------------------------------------------------------------------------
// TF32 mma.sync GEMM, cp.async 3-stage pipeline over permuted gmem tiles.
// Block tile 128(M) x 128(N) x 32(K), 256 threads.
// 8 warps in a 4(M) x 2(N) grid -> warp tile 32x64 (2x8 m16n8k8).
// Per kkb per warp: 16 MMAs vs 10 LDS (vs 8:6 before); B reuse doubled.
// ---------------------------------------------------------------------------
#define STAGES 3
#define STGW 8192            // words per stage: 4096 A + 4096 B
#define STGB 32768           // bytes per stage

template<bool ISOUT>
__global__ void __launch_bounds__(256, 2) gemm_mm(float* __restrict__ Yout)
{
    extern __shared__ __align__(16) uint32_t dsm[];   // STAGES*STGW words = 96 KB

    const int z = blockIdx.z;
    const float* A = ISOUT ? g_wkv : g_x;
    const float* W = ISOUT ? g_wo : (z == 0 ? g_wk : (z == 1 ? g_wv : g_wr2));
    float* Y       = ISOUT ? Yout : (z == 0 ? g_k : (z == 1 ? g_v : g_r));

    const int tid  = threadIdx.x;
    const int warp = tid >> 5, lane = tid & 31;
    const int mblk = blockIdx.y, nblk2 = blockIdx.x;   // 128-row, 128-col tiles
    const int wm   = warp & 3;          // 4 warps cover M (32 rows each)
    const int wn   = warp >> 2;         // 2 warps cover N (64 cols each)
    const int grp  = lane >> 2, qid = lane & 3;

    const uint32_t sbase = smem_u32(dsm);

    auto load_stage = [&](int slot, int kblk) {
        const uint32_t sb = sbase + slot * STGB;
        const float* at = A + (size_t)(mblk * 32 + kblk) * 4096;
#pragma unroll
        for (int i = 0; i < 4; i++) {               // 1024 A chunks
            const int ch = tid + (i << 8);
            cp16(sb + ch * 16, at + ch * 4);
        }
#pragma unroll
        for (int h = 0; h < 2; h++) {               // two 64-col B halves
            const float* bt = W + (size_t)((nblk2 * 2 + h) * 32 + kblk) * 2048;
#pragma unroll
            for (int i = 0; i < 2; i++) {           // 512 chunks per half
                const int ch = tid + (i << 8);
                cp16(sb + 16384 + h * 8192 + ch * 16, bt + ch * 4);
            }
        }
    };

    float acc[2][8][4];
#pragma unroll
    for (int a = 0; a < 2; a++)
#pragma unroll
        for (int b = 0; b < 8; b++)
#pragma unroll
            for (int c = 0; c < 4; c++) acc[a][b][c] = 0.f;

    load_stage(0, 0); cp_commit();
    load_stage(1, 1); cp_commit();

    for (int i = 0; i < 32; i++) {
        if (i < 31) cp_wait<1>(); else cp_wait<0>();
        __syncthreads();
        if (i + 2 < 32) { load_stage((i + 2) % 3, i + 2); cp_commit(); }

        const uint32_t* stA = dsm + (i % 3) * STGW;
        const uint32_t* stB = stA + 4096 + (wn << 11);   // this warp's 64-col half
#pragma unroll
        for (int kkb = 0; kkb < 4; kkb++) {
            uint32_t af[2][4], bf[8][2];
#pragma unroll
            for (int mt = 0; mt < 2; mt++)
                *(uint4*)af[mt] =
                    *(const uint4*)&stA[(((wm << 1) + mt) << 9) + (kkb << 7) + (grp << 4) + (qid << 2)];
#pragma unroll
            for (int nt = 0; nt < 8; nt++)
                *(uint2*)bf[nt] =
                    *(const uint2*)&stB[(nt << 8) + (kkb << 6) + (grp << 3) + (qid << 1)];
#pragma unroll
            for (int mt = 0; mt < 2; mt++)
#pragma unroll
                for (int nt = 0; nt < 8; nt++) {
                    asm volatile(
                        "mma.sync.aligned.m16n8k8.row.col.f32.tf32.tf32.f32 "
                        "{%0,%1,%2,%3}, {%4,%5,%6,%7}, {%8,%9}, {%0,%1,%2,%3};"
                        : "+f"(acc[mt][nt][0]), "+f"(acc[mt][nt][1]),
                          "+f"(acc[mt][nt][2]), "+f"(acc[mt][nt][3])
                        : "r"(af[mt][0]), "r"(af[mt][1]), "r"(af[mt][2]), "r"(af[mt][3]),
                          "r"(bf[nt][0]), "r"(bf[nt][1]));
                }
        }
    }

    // --- epilogue (linear output) ---
    const int m0 = mblk * 128, n0 = nblk2 * 128 + wn * 64;
#pragma unroll
    for (int mt = 0; mt < 2; mt++)
#pragma unroll
        for (int nt = 0; nt < 8; nt++) {
            const int row = m0 + ((wm << 1) + mt) * 16 + grp;
            const int col = n0 + (nt << 3) + (qid << 1);
            float o0 = acc[mt][nt][0], o1 = acc[mt][nt][1];
            float o2 = acc[mt][nt][2], o3 = acc[mt][nt][3];
            if (!ISOUT && z == 2) {
                o0 = 1.f / (1.f + __expf(-o0));
                o1 = 1.f / (1.f + __expf(-o1));
                o2 = 1.f / (1.f + __expf(-o2));
                o3 = 1.f / (1.f + __expf(-o3));
            }
            *(float2*)(Y + (size_t)row * CC + col)       = make_float2(o0, o1);
            *(float2*)(Y + (size_t)(row + 8) * CC + col) = make_float2(o2, o3);
        }
}

// ---------------------------------------------------------------------------
// WKV chunked parallel scan (math unchanged from the passing R4 kernel;
// scan_out fuses r-multiply + tf32 rounding + permuted write for OUT GEMM).
// ---------------------------------------------------------------------------
__global__ void __launch_bounds__(256) scan_states(const float* __restrict__ td)
{
    const int bid   = blockIdx.x;            // 512 blocks
    const int b     = bid >> 7;
    const int chunk = (bid >> 2) & 31;
    const int c     = ((bid & 3) << 8) + threadIdx.x;

    const float w = expf(td[c]);
    const size_t base = (size_t)b * TT * CC + (size_t)chunk * CLEN * CC + c;
    const float* kp = g_k + base;
    const float* vp = g_v + base;

    float aa = 0.f, bb = 0.f, pp = -1e38f;
#pragma unroll 4
    for (int t = 0; t < CLEN; t++) {
        const float kt = kp[(size_t)t * CC];
        const float vt = vp[(size_t)t * CC];
        const float ww2 = pp - w;
        const float p2  = fmaxf(ww2, kt);
        const float e1b = __expf(ww2 - p2);
        const float e2b = __expf(kt - p2);
        aa = e1b * aa + e2b * vt;
        bb = e1b * bb + e2b;
        pp = p2;
    }
    const int i = b * CC + c;
    g_saa[chunk][i] = aa; g_sbb[chunk][i] = bb; g_spp[chunk][i] = pp;
}

__global__ void __launch_bounds__(256) scan_combine(const float* __restrict__ td,
                                                    const float* __restrict__ aa0,
                                                    const float* __restrict__ bb0,
                                                    const float* __restrict__ pp0)
{
    const int i = blockIdx.x * 256 + threadIdx.x;   // [0, 4096)
    const int c = i & (CC - 1);
    const float w   = expf(td[c]);
    const float dec = (float)CLEN * w;

    float aa = aa0[i], bb = bb0[i], pp = pp0[i];
#pragma unroll
    for (int ch = 0; ch < NCH; ch++) {
        g_iaa[ch][i] = aa; g_ibb[ch][i] = bb; g_ipp[ch][i] = pp;
        const float ppd = pp - dec;
        const float aL = g_saa[ch][i], bL = g_sbb[ch][i], pL = g_spp[ch][i];
        const float p  = fmaxf(ppd, pL);
        const float e1 = __expf(ppd - p);
        const float e2 = __expf(pL - p);
        aa = e1 * aa + e2 * aL;
        bb = e1 * bb + e2 * bL;
        pp = p;
    }
}

__global__ void __launch_bounds__(256) scan_out(const float* __restrict__ td,
                                                const float* __restrict__ tf,
                                                float* __restrict__ out_tail)
{
    const int bid   = blockIdx.x;            // 512 blocks
    const int b     = bid >> 7;
    const int chunk = (bid >> 2) & 31;
    const int c     = ((bid & 3) << 8) + threadIdx.x;
    const int i     = b * CC + c;

    const float w = expf(td[c]);
    const float u = tf[c];
    float aa = g_iaa[chunk][i], bb = g_ibb[chunk][i], pp = g_ipp[chunk][i];

    const size_t base = (size_t)b * TT * CC + (size_t)chunk * CLEN * CC + c;
    const float* kp = g_k + base;
    const float* vp = g_v + base;
    const float* rp = g_r + base;
    const int mbase = b * TT + chunk * CLEN;

#pragma unroll 4
    for (int t = 0; t < CLEN; t++) {
        const float kt = kp[(size_t)t * CC];
        const float vt = vp[(size_t)t * CC];
        // output (state BEFORE update) — reference op sequence
        const float ww = u + kt;
        const float p  = fmaxf(pp, ww);
        const float e1 = __expf(pp - p);
        const float e2 = __expf(ww - p);
        const float wkv = __fdividef(e1 * aa + e2 * vt, e1 * bb + e2);
        // fused r-multiply + tf32 rounding + permuted write for OUT GEMM
        g_wkv[a_perm_idx(mbase + t, c)] =
            __uint_as_float(f2tf32(rp[(size_t)t * CC] * wkv));
        // state update
        const float ww2 = pp - w;
        const float p2  = fmaxf(ww2, kt);
        const float e1b = __expf(ww2 - p2);
        const float e2b = __expf(kt - p2);
        aa = e1b * aa + e2b * vt;
        bb = e1b * bb + e2b;
        pp = p2;
    }

    if (chunk == NCH - 1) {
        out_tail[i]           = aa;
        out_tail[NBC + i]     = bb;
        out_tail[2 * NBC + i] = pp;
    }
}

// ---------------------------------------------------------------------------
// Launch
// ---------------------------------------------------------------------------
extern "C" void kernel_launch(void* const* d_in, const int* in_sizes, int n_in,
                              void* d_out, int out_size)
{
    const float* x    = (const float*)d_in[0];
    const float* kw   = (const float*)d_in[1];
    const float* vw   = (const float*)d_in[2];
    const float* rw   = (const float*)d_in[3];
    const float* ow   = (const float*)d_in[4];
    const float* td   = (const float*)d_in[5];
    const float* tf   = (const float*)d_in[6];
    const float* aa0  = (const float*)d_in[7];
    const float* bb0  = (const float*)d_in[8];
    const float* pp0  = (const float*)d_in[9];

    float* out  = (float*)d_out;
    float* tail = out + (size_t)BTC;

    static bool configured = false;
    if (!configured) {
        cudaFuncSetAttribute(gemm_mm<false>, cudaFuncAttributeMaxDynamicSharedMemorySize,
                             STAGES * STGB);
        cudaFuncSetAttribute(gemm_mm<true>,  cudaFuncAttributeMaxDynamicSharedMemorySize,
                             STAGES * STGB);
        configured = true;
    }

    // pre-round to tf32 + fragment-permute into gmem
    round_x<<<2048, 256>>>(x);
    round_w<<<dim3(64, 4), 256>>>(kw, vw, rw, ow);

    // fused k/v/r projections (128x128 tiles)
    gemm_mm<false><<<dim3(8, 128, 3), 256, STAGES * STGB>>>(nullptr);

    // chunked parallel WKV scan
    scan_states<<<512, 256>>>(td);
    scan_combine<<<16, 256>>>(td, aa0, bb0, pp0);
    scan_out<<<512, 256>>>(td, tf, tail);

    // out = (r * wkv) @ ow^T  (A pre-multiplied, rounded, permuted by scan_out)
    gemm_mm<true><<<dim3(8, 128, 1), 256, STAGES * STGB>>>(out);
}

// round 8
// speedup vs baseline: 5.3051x; 1.6635x over previous
#include <cuda_runtime.h>
#include <cuda_fp16.h>
#include <cstdint>
#include <cstddef>

// Problem sizes (fixed)
#define BB 4
#define TT 4096
#define CC 1024
#define MM (BB * TT)          // 16384
#define BTC (BB * TT * CC)    // 16,777,216
#define NCH 32                // scan chunks along T
#define CLEN (TT / NCH)       // 128
#define NBC (BB * CC)         // 4096
#define WSZ (CC * CC)         // 1,048,576

// ---------------------------------------------------------------------------
// Scratch in device globals (no cudaMalloc allowed)
// fp16 operands stored as packed half2 words, fragment-permuted so the GEMM
// mainloop is pure cp.async -> vectorized LDS -> mma.sync (m16n8k16 f16).
// ---------------------------------------------------------------------------
__device__ __align__(16) float    g_k[BTC];
__device__ __align__(16) float    g_v[BTC];
__device__ __align__(16) float    g_r[BTC];
__device__ __align__(16) uint32_t g_x16[BTC / 2];     // permuted fp16 x
__device__ __align__(16) uint32_t g_wkv16[BTC / 2];   // permuted fp16 (r*wkv)
__device__ __align__(16) uint32_t g_wk16[WSZ / 2], g_wv16[WSZ / 2],
                                  g_wr16[WSZ / 2], g_wo16[WSZ / 2];
// chunk-local end states (from identity init) and combined incoming states
__device__ float g_saa[NCH][NBC], g_sbb[NCH][NBC], g_spp[NCH][NBC];
__device__ float g_iaa[NCH][NBC], g_ibb[NCH][NBC], g_ipp[NCH][NBC];

// ---------------------------------------------------------------------------
// Helpers
// ---------------------------------------------------------------------------
__device__ __forceinline__ uint32_t smem_u32(const void* p) {
    return (uint32_t)__cvta_generic_to_shared(p);
}
__device__ __forceinline__ void cp16(uint32_t smem_dst, const void* gmem_src) {
    asm volatile("cp.async.cg.shared.global [%0], [%1], 16;\n" :: "r"(smem_dst), "l"(gmem_src));
}
__device__ __forceinline__ void cp_commit() { asm volatile("cp.async.commit_group;\n"); }
template<int N>
__device__ __forceinline__ void cp_wait() { asm volatile("cp.async.wait_group %0;\n" :: "n"(N)); }

__device__ __forceinline__ uint32_t pack_h2(float lo, float hi) {
    const __half2 h = __floats2half2_rn(lo, hi);   // lo -> low 16 bits
    return *(const uint32_t*)&h;
}

// Fragment-permuted tile layouts over half2 words (p = k >> 1, pair index).
// K-chunk = 64 elements = 32 pairs.
// A tile per (mblk=m>>7, kblk=p>>5): 4096 words.
__device__ __forceinline__ size_t a16_idx(int m, int p) {
    const int mblk = m >> 7, kblk = p >> 5, r = m & 127, pq = p & 31;
    return (size_t)(mblk * 16 + kblk) * 4096 +
           ((r >> 4) << 9) + ((pq >> 3) << 7) + ((r & 7) << 4) +
           ((pq & 3) << 2) + (((pq >> 2) & 1) << 1) + ((r >> 3) & 1);
}
// B tile per (nblk=n>>6, kblk=p>>5): 2048 words.
__device__ __forceinline__ size_t b16_idx(int n, int p) {
    const int nblk = n >> 6, kblk = p >> 5, r = n & 63, pq = p & 31;
    return (size_t)(nblk * 16 + kblk) * 2048 +
           ((r >> 3) << 8) + ((pq >> 3) << 6) + ((r & 7) << 3) +
           ((pq & 3) << 1) + ((pq >> 2) & 1);
}

// ---------------------------------------------------------------------------
// Pre-passes: fp16-round + fragment-permute into gmem
// ---------------------------------------------------------------------------
__global__ void __launch_bounds__(256) round_x(const float* __restrict__ x)
{
    const int n4 = BTC / 4;
    for (int f = blockIdx.x * 256 + threadIdx.x; f < n4; f += gridDim.x * 256) {
        const int m = f >> 8, c0 = (f & 255) << 2;
        const float4 v = ((const float4*)x)[f];
        const size_t base = a16_idx(m, c0 >> 1);    // c0 multiple of 4 -> p even
        g_x16[base]     = pack_h2(v.x, v.y);
        g_x16[base + 4] = pack_h2(v.z, v.w);        // p+1 -> (pq&3)+1 -> +4 words
    }
}

__global__ void __launch_bounds__(256) round_w(const float* __restrict__ kw,
                                               const float* __restrict__ vw,
                                               const float* __restrict__ rw,
                                               const float* __restrict__ ow)
{
    const int z = blockIdx.y;
    const float* src = z == 0 ? kw : (z == 1 ? vw : (z == 2 ? rw : ow));
    uint32_t* dst    = z == 0 ? g_wk16 : (z == 1 ? g_wv16 : (z == 2 ? g_wr16 : g_wo16));
    const int n4 = WSZ / 4;
    for (int f = blockIdx.x * 256 + threadIdx.x; f < n4; f += gridDim.x * 256) {
        const int n = f >> 8, c0 = (f & 255) << 2;
        const float4 v = ((const float4*)src)[f];
        const size_t base = b16_idx(n, c0 >> 1);
        dst[base]     = pack_h2(v.x, v.y);
        dst[base + 2] = pack_h2(v.z, v.w);          // p+1 -> (pq&3)+1 -> +2 words
    }
}

// ---------------------------------------------------------------------------
// FP16 mma.sync GEMM (m16n8k16), cp.async 3-stage pipeline over permuted gmem.
// Block tile 128(M) x 128(N) x 64(K), 256 threads.
// 8 warps in 4(M) x 2(N) grid -> warp tile 32x64 (2x8 m16n8k16 per k16-step).
// ---------------------------------------------------------------------------
#define STAGES 3
#define STGW 8192            // words per stage: 4096 A + 4096 B (2 x 2048)
#define STGB 32768           // bytes per stage
#define NKC 16               // 1024 / 64

template<bool ISOUT>
__global__ void __launch_bounds__(256, 2) gemm_mm(float* __restrict__ Yout)
{
    extern __shared__ __align__(16) uint32_t dsm[];   // STAGES*STGW words = 96 KB

    const int z = blockIdx.z;
    const uint32_t* A = ISOUT ? g_wkv16 : g_x16;
    const uint32_t* W = ISOUT ? g_wo16 : (z == 0 ? g_wk16 : (z == 1 ? g_wv16 : g_wr16));
    float* Y          = ISOUT ? Yout : (z == 0 ? g_k : (z == 1 ? g_v : g_r));

    const int tid  = threadIdx.x;
    const int warp = tid >> 5, lane = tid & 31;
    const int mblk = blockIdx.y, nblk2 = blockIdx.x;   // 128-row, 128-col tiles
    const int wm   = warp & 3;          // 4 warps cover M (32 rows each)
    const int wn   = warp >> 2;         // 2 warps cover N (64 cols each)
    const int grp  = lane >> 2, qid = lane & 3;

    const uint32_t sbase = smem_u32(dsm);

    auto load_stage = [&](int slot, int kblk) {
        const uint32_t sb = sbase + slot * STGB;
        const uint32_t* at = A + (size_t)(mblk * 16 + kblk) * 4096;
#pragma unroll
        for (int i = 0; i < 4; i++) {               // 1024 A 16B-chunks
            const int ch = tid + (i << 8);
            cp16(sb + ch * 16, at + ch * 4);
        }
#pragma unroll
        for (int h = 0; h < 2; h++) {               // two 64-col B halves
            const uint32_t* bt = W + (size_t)((nblk2 * 2 + h) * 16 + kblk) * 2048;
#pragma unroll
            for (int i = 0; i < 2; i++) {           // 512 chunks per half
                const int ch = tid + (i << 8);
                cp16(sb + 16384 + h * 8192 + ch * 16, bt + ch * 4);
            }
        }
    };

    float acc[2][8][4];
#pragma unroll
    for (int a = 0; a < 2; a++)
#pragma unroll
        for (int b = 0; b < 8; b++)
#pragma unroll
            for (int c = 0; c < 4; c++) acc[a][b][c] = 0.f;

    load_stage(0, 0); cp_commit();
    load_stage(1, 1); cp_commit();

    for (int i = 0; i < NKC; i++) {
        if (i < NKC - 1) cp_wait<1>(); else cp_wait<0>();
        __syncthreads();
        if (i + 2 < NKC) { load_stage((i + 2) % 3, i + 2); cp_commit(); }

        const uint32_t* stA = dsm + (i % 3) * STGW;
        const uint32_t* stB = stA + 4096 + (wn << 11);   // this warp's 64-col half
#pragma unroll
        for (int s = 0; s < 4; s++) {                     // 4 k16-steps per chunk
            uint32_t af[2][4], bf[8][2];
#pragma unroll
            for (int mt = 0; mt < 2; mt++)
                *(uint4*)af[mt] =
                    *(const uint4*)&stA[(((wm << 1) + mt) << 9) + (s << 7) + (grp << 4) + (qid << 2)];
#pragma unroll
            for (int nt = 0; nt < 8; nt++)
                *(uint2*)bf[nt] =
                    *(const uint2*)&stB[(nt << 8) + (s << 6) + (grp << 3) + (qid << 1)];
#pragma unroll
            for (int mt = 0; mt < 2; mt++)
#pragma unroll
                for (int nt = 0; nt < 8; nt++) {
                    asm volatile(
                        "mma.sync.aligned.m16n8k16.row.col.f32.f16.f16.f32 "
                        "{%0,%1,%2,%3}, {%4,%5,%6,%7}, {%8,%9}, {%0,%1,%2,%3};"
                        : "+f"(acc[mt][nt][0]), "+f"(acc[mt][nt][1]),
                          "+f"(acc[mt][nt][2]), "+f"(acc[mt][nt][3])
                        : "r"(af[mt][0]), "r"(af[mt][1]), "r"(af[mt][2]), "r"(af[mt][3]),
                          "r"(bf[nt][0]), "r"(bf[nt][1]));
                }
        }
    }

    // --- epilogue (linear output, fp32) ---
    const int m0 = mblk * 128, n0 = nblk2 * 128 + wn * 64;
#pragma unroll
    for (int mt = 0; mt < 2; mt++)
#pragma unroll
        for (int nt = 0; nt < 8; nt++) {
            const int row = m0 + ((wm << 1) + mt) * 16 + grp;
            const int col = n0 + (nt << 3) + (qid << 1);
            float o0 = acc[mt][nt][0], o1 = acc[mt][nt][1];
            float o2 = acc[mt][nt][2], o3 = acc[mt][nt][3];
            if (!ISOUT && z == 2) {
                o0 = 1.f / (1.f + __expf(-o0));
                o1 = 1.f / (1.f + __expf(-o1));
                o2 = 1.f / (1.f + __expf(-o2));
                o3 = 1.f / (1.f + __expf(-o3));
            }
            *(float2*)(Y + (size_t)row * CC + col)       = make_float2(o0, o1);
            *(float2*)(Y + (size_t)(row + 8) * CC + col) = make_float2(o2, o3);
        }
}

// ---------------------------------------------------------------------------
// WKV chunked parallel scan (math unchanged from the passing kernels;
// scan_out fuses r-multiply + fp16 pack + permuted write for the OUT GEMM).
// ---------------------------------------------------------------------------
__global__ void __launch_bounds__(256) scan_states(const float* __restrict__ td)
{
    const int bid   = blockIdx.x;            // 512 blocks
    const int b     = bid >> 7;
    const int chunk = (bid >> 2) & 31;
    const int c     = ((bid & 3) << 8) + threadIdx.x;

    const float w = expf(td[c]);
    const size_t base = (size_t)b * TT * CC + (size_t)chunk * CLEN * CC + c;
    const float* kp = g_k + base;
    const float* vp = g_v + base;

    float aa = 0.f, bb = 0.f, pp = -1e38f;
#pragma unroll 4
    for (int t = 0; t < CLEN; t++) {
        const float kt = kp[(size_t)t * CC];
        const float vt = vp[(size_t)t * CC];
        const float ww2 = pp - w;
        const float p2  = fmaxf(ww2, kt);
        const float e1b = __expf(ww2 - p2);
        const float e2b = __expf(kt - p2);
        aa = e1b * aa + e2b * vt;
        bb = e1b * bb + e2b;
        pp = p2;
    }
    const int i = b * CC + c;
    g_saa[chunk][i] = aa; g_sbb[chunk][i] = bb; g_spp[chunk][i] = pp;
}

__global__ void __launch_bounds__(256) scan_combine(const float* __restrict__ td,
                                                    const float* __restrict__ aa0,
                                                    const float* __restrict__ bb0,
                                                    const float* __restrict__ pp0)
{
    const int i = blockIdx.x * 256 + threadIdx.x;   // [0, 4096)
    const int c = i & (CC - 1);
    const float w   = expf(td[c]);
    const float dec = (float)CLEN * w;

    float aa = aa0[i], bb = bb0[i], pp = pp0[i];
#pragma unroll
    for (int ch = 0; ch < NCH; ch++) {
        g_iaa[ch][i] = aa; g_ibb[ch][i] = bb; g_ipp[ch][i] = pp;
        const float ppd = pp - dec;
        const float aL = g_saa[ch][i], bL = g_sbb[ch][i], pL = g_spp[ch][i];
        const float p  = fmaxf(ppd, pL);
        const float e1 = __expf(ppd - p);
        const float e2 = __expf(pL - p);
        aa = e1 * aa + e2 * aL;
        bb = e1 * bb + e2 * bL;
        pp = p;
    }
}

__global__ void __launch_bounds__(256) scan_out(const float* __restrict__ td,
                                                const float* __restrict__ tf,
                                                float* __restrict__ out_tail)
{
    const int bid   = blockIdx.x;            // 512 blocks
    const int b     = bid >> 7;
    const int chunk = (bid >> 2) & 31;
    const int tid   = threadIdx.x;
    const int c     = ((bid & 3) << 8) + tid;
    const int i     = b * CC + c;

    const float w = expf(td[c]);
    const float u = tf[c];
    float aa = g_iaa[chunk][i], bb = g_ibb[chunk][i], pp = g_ipp[chunk][i];

    const size_t base = (size_t)b * TT * CC + (size_t)chunk * CLEN * CC + c;
    const float* kp = g_k + base;
    const float* vp = g_v + base;
    const float* rp = g_r + base;
    const int mbase = b * TT + chunk * CLEN;
    const bool even = (tid & 1) == 0;

#pragma unroll 4
    for (int t = 0; t < CLEN; t++) {
        const float kt = kp[(size_t)t * CC];
        const float vt = vp[(size_t)t * CC];
        // output (state BEFORE update) — reference op sequence
        const float ww = u + kt;
        const float p  = fmaxf(pp, ww);
        const float e1 = __expf(pp - p);
        const float e2 = __expf(ww - p);
        const float wkv = __fdividef(e1 * aa + e2 * vt, e1 * bb + e2);
        // fused r-multiply + fp16 pack (pair adjacent channels) + permuted write
        const __half h = __float2half_rn(rp[(size_t)t * CC] * wkv);
        const uint32_t hb = (uint32_t)__half_as_ushort(h);
        const uint32_t ob = __shfl_xor_sync(0xFFFFFFFFu, hb, 1);
        if (even)
            g_wkv16[a16_idx(mbase + t, c >> 1)] = hb | (ob << 16);
        // state update
        const float ww2 = pp - w;
        const float p2  = fmaxf(ww2, kt);
        const float e1b = __expf(ww2 - p2);
        const float e2b = __expf(kt - p2);
        aa = e1b * aa + e2b * vt;
        bb = e1b * bb + e2b;
        pp = p2;
    }

    if (chunk == NCH - 1) {
        out_tail[i]           = aa;
        out_tail[NBC + i]     = bb;
        out_tail[2 * NBC + i] = pp;
    }
}

// ---------------------------------------------------------------------------
// Launch
// ---------------------------------------------------------------------------
extern "C" void kernel_launch(void* const* d_in, const int* in_sizes, int n_in,
                              void* d_out, int out_size)
{
    const float* x    = (const float*)d_in[0];
    const float* kw   = (const float*)d_in[1];
    const float* vw   = (const float*)d_in[2];
    const float* rw   = (const float*)d_in[3];
    const float* ow   = (const float*)d_in[4];
    const float* td   = (const float*)d_in[5];
    const float* tf   = (const float*)d_in[6];
    const float* aa0  = (const float*)d_in[7];
    const float* bb0  = (const float*)d_in[8];
    const float* pp0  = (const float*)d_in[9];

    float* out  = (float*)d_out;
    float* tail = out + (size_t)BTC;

    static bool configured = false;
    if (!configured) {
        cudaFuncSetAttribute(gemm_mm<false>, cudaFuncAttributeMaxDynamicSharedMemorySize,
                             STAGES * STGB);
        cudaFuncSetAttribute(gemm_mm<true>,  cudaFuncAttributeMaxDynamicSharedMemorySize,
                             STAGES * STGB);
        configured = true;
    }

    // pre-round to fp16 + fragment-permute into gmem
    round_x<<<2048, 256>>>(x);
    round_w<<<dim3(64, 4), 256>>>(kw, vw, rw, ow);

    // fused k/v/r projections (128x128 tiles)
    gemm_mm<false><<<dim3(8, 128, 3), 256, STAGES * STGB>>>(nullptr);

    // chunked parallel WKV scan
    scan_states<<<512, 256>>>(td);
    scan_combine<<<16, 256>>>(td, aa0, bb0, pp0);
    scan_out<<<512, 256>>>(td, tf, tail);

    // out = (r * wkv) @ ow^T  (A pre-multiplied, packed, permuted by scan_out)
    gemm_mm<true><<<dim3(8, 128, 1), 256, STAGES * STGB>>>(out);
}